// round 1
// baseline (speedup 1.0000x reference)
#include <cuda_runtime.h>
#include <math.h>
#include <stdint.h>

// Problem constants
#define NN   32768      // nodes
#define HH   256        // hidden
#define FD   128        // input feature dim
#define BB   256        // graphs
#define MAXN 128        // nodes per graph
#define EE   524288     // edges
#define EPG  2048       // edges per graph (EE/BB)

// ---------------- scratch (device globals; no allocation allowed) ----------------
__device__ __align__(256) float g_bufA[(size_t)NN * HH];   // hw / zw
__device__ __align__(256) float g_bufB[(size_t)NN * HH];   // agg / h1 / h2
__device__ __align__(256) float g_bufC[(size_t)NN * HH];   // shortcut / bn'ed h
__device__ __align__(256) float g_z[(size_t)NN * HH];      // current activations
__device__ float g_dinv[NN];
__device__ int   g_deg[NN];        // edge-only in-degree
__device__ int   g_rowstart[NN];
__device__ int   g_cursor[NN];
__device__ int   g_csr_src[EE];    // local src index within graph
__device__ float g_csr_norm[EE];
__device__ float g_stats[2 * HH];  // [0:256) col sums, [256:512) col sumsq
__device__ __align__(256) float g_zg[BB * HH];
__device__ __align__(256) float g_small[BB * HH];

// ---------------- precompute: degrees, dinv, CSR ----------------
__global__ void k_zero_deg() {
    int n = blockIdx.x * 256 + threadIdx.x;
    if (n < NN) g_deg[n] = 0;
}

__global__ void k_count_deg(const int* __restrict__ dst) {
    int e = blockIdx.x * 256 + threadIdx.x;
    if (e >= EE) return;
    int g = e >> 11;  // e / EPG
    atomicAdd(&g_deg[g * MAXN + dst[e]], 1);
}

__global__ void k_dinv() {
    int n = blockIdx.x * 256 + threadIdx.x;
    if (n >= NN) return;
    // self loop adds 1; deg >= 1 always
    g_dinv[n] = rsqrtf((float)(g_deg[n] + 1));
}

__global__ void k_scan_rows() {
    // one CTA (128 threads) per graph: exclusive scan of edge degrees
    int g = blockIdx.x;
    int t = threadIdx.x;
    int n = g * MAXN + t;
    __shared__ int s[MAXN];
    int d = g_deg[n];
    s[t] = d;
    __syncthreads();
    for (int off = 1; off < MAXN; off <<= 1) {
        int v = (t >= off) ? s[t - off] : 0;
        __syncthreads();
        s[t] += v;
        __syncthreads();
    }
    int start = g * EPG + s[t] - d;  // exclusive prefix
    g_rowstart[n] = start;
    g_cursor[n] = start;
}

__global__ void k_fill_csr(const int* __restrict__ src, const int* __restrict__ dst) {
    int e = blockIdx.x * 256 + threadIdx.x;
    if (e >= EE) return;
    int g = e >> 11;
    int s = src[e], d = dst[e];
    int slot = atomicAdd(&g_cursor[g * MAXN + d], 1);
    g_csr_src[slot] = s;
    g_csr_norm[slot] = g_dinv[g * MAXN + s] * g_dinv[g * MAXN + d];
}

// ---------------- generic fp32 GEMM: C = A[M,K] @ W[K,N] (+bias)(+relu) ----------------
// BM=BN=128, BK=8, 256 threads, 8x8 microtile via split-float4 (conflict-free).
// Requires M%128==0, N%128==0, K%8==0 (true for all call sites).
__global__ void gemm128(const float* __restrict__ A, const float* __restrict__ W,
                        const float* __restrict__ bias, float* __restrict__ C,
                        int M, int Nn, int K, int do_relu)
{
    __shared__ float As[8][128];
    __shared__ float Bs[8][128];
    const int bm = blockIdx.y * 128, bn = blockIdx.x * 128;
    const int tid = threadIdx.x;
    const int tx = tid & 15, ty = tid >> 4;

    float acc[8][8];
#pragma unroll
    for (int i = 0; i < 8; i++)
#pragma unroll
        for (int j = 0; j < 8; j++) acc[i][j] = 0.f;

    const int lm = tid >> 1, lkq = tid & 1;   // A loader: row lm, k-quad lkq
    const int lk = tid >> 5, lnq = tid & 31;  // B loader: k row lk, n-quad lnq

    for (int k0 = 0; k0 < K; k0 += 8) {
        float4 va = *(const float4*)(A + (size_t)(bm + lm) * K + k0 + lkq * 4);
        float4 vb = *(const float4*)(W + (size_t)(k0 + lk) * Nn + bn + lnq * 4);
        As[lkq * 4 + 0][lm] = va.x;
        As[lkq * 4 + 1][lm] = va.y;
        As[lkq * 4 + 2][lm] = va.z;
        As[lkq * 4 + 3][lm] = va.w;
        *(float4*)&Bs[lk][lnq * 4] = vb;
        __syncthreads();
#pragma unroll
        for (int k = 0; k < 8; k++) {
            float a[8], b[8];
            *(float4*)(a)     = *(float4*)&As[k][ty * 4];
            *(float4*)(a + 4) = *(float4*)&As[k][64 + ty * 4];
            *(float4*)(b)     = *(float4*)&Bs[k][tx * 4];
            *(float4*)(b + 4) = *(float4*)&Bs[k][64 + tx * 4];
#pragma unroll
            for (int i = 0; i < 8; i++)
#pragma unroll
                for (int j = 0; j < 8; j++) acc[i][j] = fmaf(a[i], b[j], acc[i][j]);
        }
        __syncthreads();
    }

    float bvals[8];
#pragma unroll
    for (int j = 0; j < 8; j++) {
        int cj = (j < 4) ? (tx * 4 + j) : (64 + tx * 4 + (j - 4));
        bvals[j] = bias ? bias[bn + cj] : 0.f;
    }
#pragma unroll
    for (int i = 0; i < 8; i++) {
        int mi = bm + ((i < 4) ? (ty * 4 + i) : (64 + ty * 4 + (i - 4)));
        float o[8];
#pragma unroll
        for (int j = 0; j < 8; j++) {
            float v = acc[i][j] + bvals[j];
            o[j] = do_relu ? fmaxf(v, 0.f) : v;
        }
        *(float4*)(C + (size_t)mi * Nn + bn + tx * 4)      = make_float4(o[0], o[1], o[2], o[3]);
        *(float4*)(C + (size_t)mi * Nn + bn + 64 + tx * 4) = make_float4(o[4], o[5], o[6], o[7]);
    }
}

// ---------------- per-graph GCN aggregation ----------------
// out[n] = dinv[n]^2 * hw[n] + sum_{e: dst=n} norm_e * hw[src_e]
// One CTA per graph; feature dim processed in 4 chunks of 64 cols (32KB smem).
__global__ void aggregate(const float* __restrict__ hw, float* __restrict__ outp) {
    __shared__ float sh[MAXN * 64];
    int g = blockIdx.x;
    int lane = threadIdx.x & 31;
    int w = threadIdx.x >> 5;
    int nbase = g * MAXN;
    for (int q = 0; q < 4; q++) {
        __syncthreads();  // protect smem reuse from previous chunk
        int c0 = q * 64;
        for (int i = threadIdx.x; i < MAXN * 16; i += 256) {
            int node = i >> 4, cq = i & 15;
            ((float4*)sh)[i] =
                *(const float4*)(hw + (size_t)(nbase + node) * HH + c0 + cq * 4);
        }
        __syncthreads();
        for (int n = w; n < MAXN; n += 8) {
            int gn = nbase + n;
            int rs = g_rowstart[gn];
            int cnt = g_deg[gn];
            float di = g_dinv[gn];
            float sl = di * di;
            const float* prow = &sh[n * 64 + lane * 2];
            float a0 = prow[0] * sl, a1 = prow[1] * sl;
            for (int e = 0; e < cnt; e++) {
                int s = g_csr_src[rs + e];
                float nm = g_csr_norm[rs + e];
                const float* p = &sh[s * 64 + lane * 2];
                a0 = fmaf(p[0], nm, a0);
                a1 = fmaf(p[1], nm, a1);
            }
            float2 o = make_float2(a0, a1);
            *(float2*)(outp + (size_t)gn * HH + c0 + lane * 2) = o;
        }
    }
}

// ---------------- BatchNorm stats + fused apply ----------------
__global__ void k_zero_stats() {
    int t = threadIdx.x;
    if (t < 2 * HH) g_stats[t] = 0.f;
}

__global__ void bn_stats(const float* __restrict__ x) {
    // 256 CTAs x 256 threads; each thread owns one column for a 128-row stripe
    int col = threadIdx.x;
    int r0 = blockIdx.x * 128;
    float s = 0.f, q = 0.f;
    for (int r = 0; r < 128; r++) {
        float v = x[(size_t)(r0 + r) * HH + col];
        s += v;
        q = fmaf(v, v, q);
    }
    atomicAdd(&g_stats[col], s);
    atomicAdd(&g_stats[HH + col], q);
}

// mode 0: out = bn(x);  mode 1: out = relu(relu(bn(x)) + res)
__global__ void bn_apply(const float* __restrict__ xin, const float* __restrict__ res,
                         const float* __restrict__ gam, const float* __restrict__ bet,
                         float* __restrict__ outp, int mode)
{
    size_t idx = (size_t)blockIdx.x * 256 + threadIdx.x;
    int col = (int)(idx & 255);
    const float invN = 1.0f / (float)NN;
    float m = g_stats[col] * invN;
    float var = fmaxf(g_stats[HH + col] * invN - m * m, 0.f);
    float a = gam[col] * rsqrtf(var + 1e-5f);
    float bp = bet[col] - m * a;
    float v = fmaf(xin[idx], a, bp);
    if (mode == 1) {
        v = fmaxf(v, 0.f);
        v = fmaxf(v + res[idx], 0.f);
    }
    outp[idx] = v;
}

// ---------------- row L2 normalize (writes scratch + d_out) ----------------
__global__ void l2norm(const float* __restrict__ zin, float* __restrict__ o1,
                       float* __restrict__ o2)
{
    int row = blockIdx.x * 8 + (threadIdx.x >> 5);
    int lane = threadIdx.x & 31;
    const float4* p = (const float4*)(zin + (size_t)row * HH);
    float4 v0 = p[lane], v1 = p[lane + 32];
    float s = v0.x * v0.x + v0.y * v0.y + v0.z * v0.z + v0.w * v0.w
            + v1.x * v1.x + v1.y * v1.y + v1.z * v1.z + v1.w * v1.w;
#pragma unroll
    for (int o = 16; o > 0; o >>= 1) s += __shfl_xor_sync(0xffffffffu, s, o);
    float inv = 1.f / fmaxf(sqrtf(s), 1e-12f);
    float4 w0 = make_float4(v0.x * inv, v0.y * inv, v0.z * inv, v0.w * inv);
    float4 w1 = make_float4(v1.x * inv, v1.y * inv, v1.z * inv, v1.w * inv);
    ((float4*)(o1 + (size_t)row * HH))[lane] = w0;
    ((float4*)(o1 + (size_t)row * HH))[lane + 32] = w1;
    ((float4*)(o2 + (size_t)row * HH))[lane] = w0;
    ((float4*)(o2 + (size_t)row * HH))[lane + 32] = w1;
}

// ---------------- per-graph edge decoder: adj = sigmoid(zw @ z^T), zero diag ----------------
__global__ void adj_kernel(const float* __restrict__ zw, const float* __restrict__ z,
                           float* __restrict__ adj)
{
    __shared__ float As[32][128];  // As[k][i] = zw[g*128+i][k0+k]
    __shared__ float Bs[32][128];  // Bs[k][j] = z [g*128+j][k0+k]
    int g = blockIdx.x;
    int tid = threadIdx.x;
    int tx = tid & 15, ty = tid >> 4;
    float acc[8][8];
#pragma unroll
    for (int i = 0; i < 8; i++)
#pragma unroll
        for (int j = 0; j < 8; j++) acc[i][j] = 0.f;

    for (int k0 = 0; k0 < HH; k0 += 32) {
        __syncthreads();
        for (int i = tid; i < MAXN * 8; i += 256) {  // 1024 float4 per matrix
            int rrow = i >> 3, kq = i & 7;
            float4 va = *(const float4*)(zw + (size_t)(g * MAXN + rrow) * HH + k0 + kq * 4);
            As[kq * 4 + 0][rrow] = va.x;
            As[kq * 4 + 1][rrow] = va.y;
            As[kq * 4 + 2][rrow] = va.z;
            As[kq * 4 + 3][rrow] = va.w;
            float4 vb = *(const float4*)(z + (size_t)(g * MAXN + rrow) * HH + k0 + kq * 4);
            Bs[kq * 4 + 0][rrow] = vb.x;
            Bs[kq * 4 + 1][rrow] = vb.y;
            Bs[kq * 4 + 2][rrow] = vb.z;
            Bs[kq * 4 + 3][rrow] = vb.w;
        }
        __syncthreads();
#pragma unroll
        for (int k = 0; k < 32; k++) {
            float a[8], b[8];
            *(float4*)(a)     = *(float4*)&As[k][ty * 4];
            *(float4*)(a + 4) = *(float4*)&As[k][64 + ty * 4];
            *(float4*)(b)     = *(float4*)&Bs[k][tx * 4];
            *(float4*)(b + 4) = *(float4*)&Bs[k][64 + tx * 4];
#pragma unroll
            for (int i = 0; i < 8; i++)
#pragma unroll
                for (int j = 0; j < 8; j++) acc[i][j] = fmaf(a[i], b[j], acc[i][j]);
        }
    }
#pragma unroll
    for (int i = 0; i < 8; i++) {
        int ri = (i < 4) ? (ty * 4 + i) : (64 + ty * 4 + (i - 4));
#pragma unroll
        for (int j = 0; j < 8; j++) {
            int cj = (j < 4) ? (tx * 4 + j) : (64 + tx * 4 + (j - 4));
            float v = 1.f / (1.f + __expf(-acc[i][j]));
            if (ri == cj) v = 0.f;
            adj[(size_t)g * (MAXN * MAXN) + (size_t)ri * MAXN + cj] = v;
        }
    }
}

// ---------------- per-graph max pool ----------------
__global__ void maxpool(const float* __restrict__ z, float* __restrict__ o1,
                        float* __restrict__ o2)
{
    int idx = blockIdx.x * 256 + threadIdx.x;  // B*H threads
    int g = idx >> 8, c = idx & 255;
    float m = -1e30f;
    const float* base = z + (size_t)g * MAXN * HH + c;
    for (int n = 0; n < MAXN; n++) m = fmaxf(m, base[(size_t)n * HH]);
    o1[idx] = m;
    o2[idx] = m;
}

// ---------------- launcher ----------------
extern "C" void kernel_launch(void* const* d_in, const int* in_sizes, int n_in,
                              void* d_out, int out_size)
{
    const float* x   = (const float*)d_in[0];
    const int*   src = (const int*)d_in[1];
    const int*   dst = (const int*)d_in[2];
    const float* gcn_w0 = (const float*)d_in[3];
    const float* bn_g0  = (const float*)d_in[5];
    const float* bn_b0  = (const float*)d_in[6];
    const float *sc_w0, *sc_b0, *gcn_w1, *bn_g1, *bn_b1, *gcn_w2, *bn_g2, *bn_b2;
    if (in_sizes[7] == FD * HH) {  // reference-signature order: sc_w0 at [7]
        sc_w0  = (const float*)d_in[7];
        sc_b0  = (const float*)d_in[8];
        gcn_w1 = (const float*)d_in[9];
        bn_g1  = (const float*)d_in[11];
        bn_b1  = (const float*)d_in[12];
        gcn_w2 = (const float*)d_in[13];
        bn_g2  = (const float*)d_in[15];
        bn_b2  = (const float*)d_in[16];
    } else {                        // setup_inputs dict order
        gcn_w1 = (const float*)d_in[7];
        bn_g1  = (const float*)d_in[9];
        bn_b1  = (const float*)d_in[10];
        gcn_w2 = (const float*)d_in[11];
        bn_g2  = (const float*)d_in[13];
        bn_b2  = (const float*)d_in[14];
        sc_w0  = (const float*)d_in[15];
        sc_b0  = (const float*)d_in[16];
    }
    const float* edge_w = (const float*)d_in[17];
    const float* fd_w0  = (const float*)d_in[18];
    const float* fd_b0  = (const float*)d_in[19];
    const float* fd_g0  = (const float*)d_in[20];
    const float* fd_be0 = (const float*)d_in[21];
    const float* fd_w1  = (const float*)d_in[22];
    const float* fd_b1  = (const float*)d_in[23];
    const float* fd_g1  = (const float*)d_in[24];
    const float* fd_be1 = (const float*)d_in[25];
    const float* fd_w2  = (const float*)d_in[26];
    const float* fd_b2  = (const float*)d_in[27];
    const float* ph_w0  = (const float*)d_in[28];
    const float* ph_b0  = (const float*)d_in[29];
    const float* ph_w1  = (const float*)d_in[30];
    const float* ph_b1  = (const float*)d_in[31];

    float* out = (float*)d_out;
    float* out_z   = out;
    float* out_adj = out + (size_t)NN * HH;
    float* out_xr  = out_adj + (size_t)BB * MAXN * MAXN;
    float* out_zg  = out_xr + (size_t)NN * FD;
    float* out_mlp = out_zg + (size_t)BB * HH;

    float *pA, *pB, *pC, *pZ, *pZg, *pSm;
    cudaGetSymbolAddress((void**)&pA,  g_bufA);
    cudaGetSymbolAddress((void**)&pB,  g_bufB);
    cudaGetSymbolAddress((void**)&pC,  g_bufC);
    cudaGetSymbolAddress((void**)&pZ,  g_z);
    cudaGetSymbolAddress((void**)&pZg, g_zg);
    cudaGetSymbolAddress((void**)&pSm, g_small);

    // ---- graph structure precompute (deterministic work, part of every launch) ----
    k_zero_deg<<<NN / 256, 256>>>();
    k_count_deg<<<EE / 256, 256>>>(dst);
    k_dinv<<<NN / 256, 256>>>();
    k_scan_rows<<<BB, 128>>>();
    k_fill_csr<<<EE / 256, 256>>>(src, dst);

    dim3 gBig(HH / 128, NN / 128);   // (2, 256)
    dim3 gXr(FD / 128, NN / 128);    // (1, 256)
    dim3 gPh(HH / 128, BB / 128);    // (2, 2)

    // ---- block 0: gcn0 + bn + relu, shortcut = x@sc_w0+sc_b0 ----
    gemm128<<<gBig, 256>>>(x, gcn_w0, nullptr, pA, NN, HH, FD, 0);
    gemm128<<<gBig, 256>>>(x, sc_w0, sc_b0, pC, NN, HH, FD, 0);
    aggregate<<<BB, 256>>>(pA, pB);
    k_zero_stats<<<1, 512>>>();
    bn_stats<<<256, 256>>>(pB);
    bn_apply<<<NN * HH / 256, 256>>>(pB, pC, bn_g0, bn_b0, pZ, 1);

    // ---- block 1: identity shortcut ----
    gemm128<<<gBig, 256>>>(pZ, gcn_w1, nullptr, pA, NN, HH, HH, 0);
    aggregate<<<BB, 256>>>(pA, pB);
    k_zero_stats<<<1, 512>>>();
    bn_stats<<<256, 256>>>(pB);
    bn_apply<<<NN * HH / 256, 256>>>(pB, pZ, bn_g1, bn_b1, pZ, 1);

    // ---- block 2 ----
    gemm128<<<gBig, 256>>>(pZ, gcn_w2, nullptr, pA, NN, HH, HH, 0);
    aggregate<<<BB, 256>>>(pA, pB);
    k_zero_stats<<<1, 512>>>();
    bn_stats<<<256, 256>>>(pB);
    bn_apply<<<NN * HH / 256, 256>>>(pB, pZ, bn_g2, bn_b2, pZ, 1);

    // ---- row-normalize -> z (output 0) ----
    l2norm<<<NN / 8, 256>>>(pZ, pZ, out_z);

    // ---- edge decoder: adj (output 1) ----
    gemm128<<<gBig, 256>>>(pZ, edge_w, nullptr, pA, NN, HH, HH, 0);
    adj_kernel<<<BB, 256>>>(pA, pZ, out_adj);

    // ---- feature decoder: x_recon (output 2) ----
    gemm128<<<gBig, 256>>>(pZ, fd_w0, fd_b0, pB, NN, HH, HH, 1);
    k_zero_stats<<<1, 512>>>();
    bn_stats<<<256, 256>>>(pB);
    bn_apply<<<NN * HH / 256, 256>>>(pB, nullptr, fd_g0, fd_be0, pC, 0);
    gemm128<<<gBig, 256>>>(pC, fd_w1, fd_b1, pB, NN, HH, HH, 1);
    k_zero_stats<<<1, 512>>>();
    bn_stats<<<256, 256>>>(pB);
    bn_apply<<<NN * HH / 256, 256>>>(pB, nullptr, fd_g1, fd_be1, pC, 0);
    gemm128<<<gXr, 256>>>(pC, fd_w2, fd_b2, out_xr, NN, FD, HH, 0);

    // ---- pooling head: z_g (output 3), z_g_mlp (output 4) ----
    maxpool<<<BB * HH / 256, 256>>>(pZ, pZg, out_zg);
    gemm128<<<gPh, 256>>>(pZg, ph_w0, ph_b0, pSm, BB, HH, HH, 1);
    gemm128<<<gPh, 256>>>(pSm, ph_w1, ph_b1, out_mlp, BB, HH, HH, 0);
}

// round 3
// speedup vs baseline: 1.3105x; 1.3105x over previous
#include <cuda_runtime.h>
#include <cuda_bf16.h>
#include <math.h>
#include <stdint.h>

// Problem constants
#define NN   32768      // nodes
#define HH   256        // hidden
#define FD   128        // input feature dim
#define BB   256        // graphs
#define MAXN 128        // nodes per graph
#define EE   524288     // edges
#define EPG  2048       // edges per graph (EE/BB)

// ======================= PTX helpers (baseline compute_100 only) =======================
__device__ __forceinline__ uint32_t smem_to_u32(const void* smem_ptr) {
    uint32_t addr;
    asm("{ .reg .u64 tmp; cvta.to.shared.u64 tmp, %1; cvt.u32.u64 %0, tmp; }"
        : "=r"(addr) : "l"(smem_ptr));
    return addr;
}
__device__ __forceinline__ void ldsm4(uint32_t* r, uint32_t addr) {
    asm volatile("ldmatrix.sync.aligned.m8n8.x4.shared.b16 {%0,%1,%2,%3}, [%4];"
        : "=r"(r[0]), "=r"(r[1]), "=r"(r[2]), "=r"(r[3]) : "r"(addr));
}
__device__ __forceinline__ void mma16816(float* d, const uint32_t* a, uint32_t b0, uint32_t b1) {
    asm volatile(
        "mma.sync.aligned.m16n8k16.row.col.f32.bf16.bf16.f32 "
        "{%0,%1,%2,%3}, {%4,%5,%6,%7}, {%8,%9}, {%0,%1,%2,%3};"
        : "+f"(d[0]), "+f"(d[1]), "+f"(d[2]), "+f"(d[3])
        : "r"(a[0]), "r"(a[1]), "r"(a[2]), "r"(a[3]), "r"(b0), "r"(b1));
}
__device__ __forceinline__ void cp16(uint32_t s, const void* g) {
    asm volatile("cp.async.cg.shared.global [%0], [%1], 16;" :: "r"(s), "l"(g) : "memory");
}
__device__ __forceinline__ void cp_commit() {
    asm volatile("cp.async.commit_group;" ::: "memory");
}
template<int NG> __device__ __forceinline__ void cp_wait() {
    asm volatile("cp.async.wait_group %0;" :: "n"(NG) : "memory");
}

// ---------------- scratch (device globals) ----------------
__device__ __align__(256) float g_bufA[(size_t)NN * HH];
__device__ __align__(256) float g_bufB[(size_t)NN * HH];
__device__ __align__(256) float g_bufC[(size_t)NN * HH];
__device__ __align__(256) float g_z[(size_t)NN * HH];
__device__ float g_dinv[NN];
__device__ int   g_deg[NN];
__device__ int   g_rowstart[NN];
__device__ int   g_cursor[NN];
__device__ int   g_csr_src[EE];
__device__ float g_csr_norm[EE];
__device__ float g_stats[2 * HH];

// bf16 hi/lo operand buffers
__device__ __align__(256) __nv_bfloat16 g_p0hi[(size_t)NN * HH];
__device__ __align__(256) __nv_bfloat16 g_p0lo[(size_t)NN * HH];
__device__ __align__(256) __nv_bfloat16 g_p1hi[(size_t)NN * HH];
__device__ __align__(256) __nv_bfloat16 g_p1lo[(size_t)NN * HH];
__device__ __align__(256) __nv_bfloat16 g_s0hi[BB * HH];
__device__ __align__(256) __nv_bfloat16 g_s0lo[BB * HH];
__device__ __align__(256) __nv_bfloat16 g_s1hi[BB * HH];
__device__ __align__(256) __nv_bfloat16 g_s1lo[BB * HH];
__device__ __align__(256) __nv_bfloat16 g_whi[10 * 65536];  // 10 transposed weights
__device__ __align__(256) __nv_bfloat16 g_wlo[10 * 65536];

// ---------------- precompute: degrees, dinv, CSR ----------------
__global__ void k_zero_deg() {
    int n = blockIdx.x * 256 + threadIdx.x;
    if (n < NN) g_deg[n] = 0;
}
__global__ void k_count_deg(const int* __restrict__ dst) {
    int e = blockIdx.x * 256 + threadIdx.x;
    if (e >= EE) return;
    int g = e >> 11;
    atomicAdd(&g_deg[g * MAXN + dst[e]], 1);
}
__global__ void k_dinv() {
    int n = blockIdx.x * 256 + threadIdx.x;
    if (n >= NN) return;
    g_dinv[n] = rsqrtf((float)(g_deg[n] + 1));
}
__global__ void k_scan_rows() {
    int g = blockIdx.x;
    int t = threadIdx.x;
    int n = g * MAXN + t;
    __shared__ int s[MAXN];
    int d = g_deg[n];
    s[t] = d;
    __syncthreads();
    for (int off = 1; off < MAXN; off <<= 1) {
        int v = (t >= off) ? s[t - off] : 0;
        __syncthreads();
        s[t] += v;
        __syncthreads();
    }
    int start = g * EPG + s[t] - d;
    g_rowstart[n] = start;
    g_cursor[n] = start;
}
__global__ void k_fill_csr(const int* __restrict__ src, const int* __restrict__ dst) {
    int e = blockIdx.x * 256 + threadIdx.x;
    if (e >= EE) return;
    int g = e >> 11;
    int s = src[e], d = dst[e];
    int slot = atomicAdd(&g_cursor[g * MAXN + d], 1);
    g_csr_src[slot] = s;
    g_csr_norm[slot] = g_dinv[g * MAXN + s] * g_dinv[g * MAXN + d];
}

// ---------------- fp32 -> bf16 hi/lo converts ----------------
__device__ __forceinline__ void split_bf16(float v, __nv_bfloat16& h, __nv_bfloat16& l) {
    h = __float2bfloat16(v);
    l = __float2bfloat16(v - __bfloat162float(h));
}
__global__ void a_conv(const float* __restrict__ A, __nv_bfloat16* __restrict__ hi,
                       __nv_bfloat16* __restrict__ lo, int n) {
    int i = blockIdx.x * 256 + threadIdx.x;
    if (i >= n) return;
    __nv_bfloat16 h, l;
    split_bf16(A[i], h, l);
    hi[i] = h; lo[i] = l;
}
// W[K,N] fp32 -> hi/lo[N,K] bf16 (transposed, K-major operand layout)
__global__ void w_conv(const float* __restrict__ W, __nv_bfloat16* __restrict__ hi,
                       __nv_bfloat16* __restrict__ lo, int Kd, int Nd) {
    int i = blockIdx.x * 256 + threadIdx.x;
    if (i >= Kd * Nd) return;
    int k = i / Nd, n = i - k * Nd;
    __nv_bfloat16 h, l;
    split_bf16(W[i], h, l);
    hi[(size_t)n * Kd + k] = h;
    lo[(size_t)n * Kd + k] = l;
}

// ======================= mma.sync split-x3 GEMM =======================
// C[M,Ncols] = A[M,K] @ B[Ncols,K]^T via bf16 hi/lo x3, fp32 accumulate.
// CTA: 128(M) x 128(N) tile, 8 warps (4x2), warp tile 32x64.
// K chunks of 32, cp.async double-buffered. SMEM rows padded to 80B.
// ADJ: B rows taken from the SAME 128-row window as A (per-graph z);
//      epilogue = sigmoid, zero diagonal, output [tile][128][128].
#define ROWB   80
#define MATB   10240            // 128 rows * 80B
#define STAGEB 40960            // 4 matrices (Ahi,Alo,Bhi,Blo)
template<bool ADJ>
__global__ void __launch_bounds__(256, 1)
mma_gemm(const __nv_bfloat16* __restrict__ Ahi, const __nv_bfloat16* __restrict__ Alo,
         const __nv_bfloat16* __restrict__ Bhi, const __nv_bfloat16* __restrict__ Blo,
         const float* __restrict__ bias, float* __restrict__ Cf,
         __nv_bfloat16* __restrict__ Chi, __nv_bfloat16* __restrict__ Clo,
         int K, int Ncols, int relu)
{
    extern __shared__ char smem[];
    const uint32_t sb = smem_to_u32(smem);
    const int tid = threadIdx.x;
    const int lane = tid & 31;
    const int wid = tid >> 5;
    const int warp_m = wid & 3;        // 4 warps along M
    const int warp_n = wid >> 2;       // 2 warps along N
    const int mrow0 = blockIdx.x * 128;
    const int bn0 = blockIdx.y * 128;
    const int brow0 = ADJ ? mrow0 : bn0;

    const __nv_bfloat16* baseA_hi = Ahi + (size_t)mrow0 * K;
    const __nv_bfloat16* baseA_lo = Alo + (size_t)mrow0 * K;
    const __nv_bfloat16* baseB_hi = Bhi + (size_t)brow0 * K;
    const __nv_bfloat16* baseB_lo = Blo + (size_t)brow0 * K;

    float acc[2][8][4];
#pragma unroll
    for (int mt = 0; mt < 2; mt++)
#pragma unroll
        for (int nt = 0; nt < 8; nt++)
#pragma unroll
            for (int v = 0; v < 4; v++) acc[mt][nt][v] = 0.f;

    auto load_chunk = [&](int c, int stage) {
        const int kc = c << 5;
        const uint32_t sbase = sb + stage * STAGEB;
#pragma unroll
        for (int t = 0; t < 8; t++) {
            int i = t * 256 + tid;
            int mat = i >> 9;               // constant per unrolled t
            int r = (i >> 2) & 127;
            int q = i & 3;
            const __nv_bfloat16* g;
            if      (mat == 0) g = baseA_hi + (size_t)r * K + kc + q * 8;
            else if (mat == 1) g = baseA_lo + (size_t)r * K + kc + q * 8;
            else if (mat == 2) g = baseB_hi + (size_t)r * K + kc + q * 8;
            else               g = baseB_lo + (size_t)r * K + kc + q * 8;
            cp16(sbase + mat * MATB + r * ROWB + q * 16, g);
        }
    };

    auto compute_chunk = [&](int stage) {
        const uint32_t sA = sb + stage * STAGEB;
        const uint32_t sB = sA + 2 * MATB;
#pragma unroll
        for (int ks = 0; ks < 2; ks++) {
            const uint32_t koff = ks * 32 + (lane >> 4) * 16;
            uint32_t ahi[2][4], alo[2][4];
#pragma unroll
            for (int mt = 0; mt < 2; mt++) {
                uint32_t ad = sA + (uint32_t)((warp_m * 32 + mt * 16 + (lane & 15)) * ROWB) + koff;
                ldsm4(ahi[mt], ad);
                ldsm4(alo[mt], ad + MATB);
            }
            uint32_t bhiR[4][4], bloR[4][4];
#pragma unroll
            for (int g4 = 0; g4 < 4; g4++) {
                uint32_t ad = sB + (uint32_t)((warp_n * 64 + g4 * 16 + (lane & 15)) * ROWB) + koff;
                ldsm4(bhiR[g4], ad);
                ldsm4(bloR[g4], ad + MATB);
            }
#pragma unroll
            for (int mt = 0; mt < 2; mt++)
#pragma unroll
                for (int nt = 0; nt < 8; nt++) {
                    int g4 = nt >> 1, s = nt & 1;
                    mma16816(acc[mt][nt], ahi[mt], bhiR[g4][s], bhiR[g4][s + 2]);
                    mma16816(acc[mt][nt], ahi[mt], bloR[g4][s], bloR[g4][s + 2]);
                    mma16816(acc[mt][nt], alo[mt], bhiR[g4][s], bhiR[g4][s + 2]);
                }
        }
    };

    const int nch = K >> 5;
    load_chunk(0, 0);
    cp_commit();
    for (int c = 0; c < nch; c++) {
        if (c + 1 < nch) {
            load_chunk(c + 1, (c + 1) & 1);
            cp_commit();
            cp_wait<1>();
        } else {
            cp_wait<0>();
        }
        __syncthreads();
        compute_chunk(c & 1);
        __syncthreads();
    }

    // ---- epilogue (register-resident) ----
    const int r0 = lane >> 2;
    const int cq = (lane & 3) * 2;
#pragma unroll
    for (int mt = 0; mt < 2; mt++) {
#pragma unroll
        for (int nt = 0; nt < 8; nt++) {
            int col = bn0 + warp_n * 64 + nt * 8 + cq;
            float bv0 = 0.f, bv1 = 0.f;
            if (bias) { bv0 = bias[col]; bv1 = bias[col + 1]; }
#pragma unroll
            for (int h = 0; h < 2; h++) {
                int row = mrow0 + warp_m * 32 + mt * 16 + r0 + h * 8;
                float v0 = acc[mt][nt][h * 2 + 0] + bv0;
                float v1 = acc[mt][nt][h * 2 + 1] + bv1;
                if (relu) { v0 = fmaxf(v0, 0.f); v1 = fmaxf(v1, 0.f); }
                if (ADJ) {
                    v0 = 1.f / (1.f + __expf(-v0));
                    v1 = 1.f / (1.f + __expf(-v1));
                    int rl = row - mrow0;       // local row within graph
                    int cl = col;               // Ncols==128, bn0==0
                    if (rl == cl) v0 = 0.f;
                    if (rl == cl + 1) v1 = 0.f;
                    float2 o = make_float2(v0, v1);
                    *(float2*)(Cf + (size_t)blockIdx.x * (MAXN * MAXN)
                               + (size_t)rl * MAXN + cl) = o;
                } else {
                    size_t o = (size_t)row * Ncols + col;
                    if (Cf) *(float2*)(Cf + o) = make_float2(v0, v1);
                    if (Chi) {
                        __nv_bfloat16 h0, l0, h1, l1;
                        split_bf16(v0, h0, l0);
                        split_bf16(v1, h1, l1);
                        __nv_bfloat162 ph = {h0, h1}, pl = {l0, l1};
                        *(__nv_bfloat162*)(Chi + o) = ph;
                        *(__nv_bfloat162*)(Clo + o) = pl;
                    }
                }
            }
        }
    }
}

// ---------------- per-graph GCN aggregation (fp32, SIMT) ----------------
__global__ void aggregate(const float* __restrict__ hw, float* __restrict__ outp) {
    __shared__ float sh[MAXN * 64];
    int g = blockIdx.x;
    int lane = threadIdx.x & 31;
    int w = threadIdx.x >> 5;
    int nbase = g * MAXN;
    for (int q = 0; q < 4; q++) {
        __syncthreads();
        int c0 = q * 64;
        for (int i = threadIdx.x; i < MAXN * 16; i += 256) {
            int node = i >> 4, cqq = i & 15;
            ((float4*)sh)[i] =
                *(const float4*)(hw + (size_t)(nbase + node) * HH + c0 + cqq * 4);
        }
        __syncthreads();
        for (int n = w; n < MAXN; n += 8) {
            int gn = nbase + n;
            int rs = g_rowstart[gn];
            int cnt = g_deg[gn];
            float di = g_dinv[gn];
            float sl = di * di;
            const float* prow = &sh[n * 64 + lane * 2];
            float a0 = prow[0] * sl, a1 = prow[1] * sl;
            for (int e = 0; e < cnt; e++) {
                int s = g_csr_src[rs + e];
                float nm = g_csr_norm[rs + e];
                const float* p = &sh[s * 64 + lane * 2];
                a0 = fmaf(p[0], nm, a0);
                a1 = fmaf(p[1], nm, a1);
            }
            *(float2*)(outp + (size_t)gn * HH + c0 + lane * 2) = make_float2(a0, a1);
        }
    }
}

// ---------------- BatchNorm stats + fused apply (+ bf16 emit) ----------------
__global__ void k_zero_stats() {
    int t = threadIdx.x;
    if (t < 2 * HH) g_stats[t] = 0.f;
}
__global__ void bn_stats(const float* __restrict__ x) {
    int col = threadIdx.x;
    int r0 = blockIdx.x * 128;
    float s = 0.f, q = 0.f;
    for (int r = 0; r < 128; r++) {
        float v = x[(size_t)(r0 + r) * HH + col];
        s += v;
        q = fmaf(v, v, q);
    }
    atomicAdd(&g_stats[col], s);
    atomicAdd(&g_stats[HH + col], q);
}
// mode 0: out = bn(x); mode 1: out = relu(relu(bn(x)) + res); optional bf16 emit
__global__ void bn_apply(const float* __restrict__ xin, const float* __restrict__ res,
                         const float* __restrict__ gam, const float* __restrict__ bet,
                         float* __restrict__ outp,
                         __nv_bfloat16* __restrict__ ohi, __nv_bfloat16* __restrict__ olo,
                         int mode)
{
    size_t idx = (size_t)blockIdx.x * 256 + threadIdx.x;
    int col = (int)(idx & 255);
    const float invN = 1.0f / (float)NN;
    float m = g_stats[col] * invN;
    float var = fmaxf(g_stats[HH + col] * invN - m * m, 0.f);
    float a = gam[col] * rsqrtf(var + 1e-5f);
    float bp = bet[col] - m * a;
    float v = fmaf(xin[idx], a, bp);
    if (mode == 1) {
        v = fmaxf(v, 0.f);
        v = fmaxf(v + res[idx], 0.f);
    }
    outp[idx] = v;
    if (ohi) {
        __nv_bfloat16 h, l;
        split_bf16(v, h, l);
        ohi[idx] = h; olo[idx] = l;
    }
}

// ---------------- row L2 normalize (+ bf16 emit) ----------------
__global__ void l2norm(const float* __restrict__ zin, float* __restrict__ o1,
                       float* __restrict__ o2,
                       __nv_bfloat16* __restrict__ ohi, __nv_bfloat16* __restrict__ olo)
{
    int row = blockIdx.x * 8 + (threadIdx.x >> 5);
    int lane = threadIdx.x & 31;
    const float4* p = (const float4*)(zin + (size_t)row * HH);
    float4 v0 = p[lane], v1 = p[lane + 32];
    float s = v0.x * v0.x + v0.y * v0.y + v0.z * v0.z + v0.w * v0.w
            + v1.x * v1.x + v1.y * v1.y + v1.z * v1.z + v1.w * v1.w;
#pragma unroll
    for (int o = 16; o > 0; o >>= 1) s += __shfl_xor_sync(0xffffffffu, s, o);
    float inv = 1.f / fmaxf(sqrtf(s), 1e-12f);
    float4 w0 = make_float4(v0.x * inv, v0.y * inv, v0.z * inv, v0.w * inv);
    float4 w1 = make_float4(v1.x * inv, v1.y * inv, v1.z * inv, v1.w * inv);
    ((float4*)(o1 + (size_t)row * HH))[lane] = w0;
    ((float4*)(o1 + (size_t)row * HH))[lane + 32] = w1;
    ((float4*)(o2 + (size_t)row * HH))[lane] = w0;
    ((float4*)(o2 + (size_t)row * HH))[lane + 32] = w1;
    const float vv[8] = {w0.x, w0.y, w0.z, w0.w, w1.x, w1.y, w1.z, w1.w};
#pragma unroll
    for (int k = 0; k < 4; k++) {
        __nv_bfloat16 h, l;
        split_bf16(vv[k], h, l);
        ohi[(size_t)row * HH + lane * 4 + k] = h;
        olo[(size_t)row * HH + lane * 4 + k] = l;
        split_bf16(vv[4 + k], h, l);
        ohi[(size_t)row * HH + 128 + lane * 4 + k] = h;
        olo[(size_t)row * HH + 128 + lane * 4 + k] = l;
    }
}

// ---------------- per-graph max pool (+ bf16 emit) ----------------
__global__ void maxpool(const float* __restrict__ z, float* __restrict__ o1,
                        __nv_bfloat16* __restrict__ ohi, __nv_bfloat16* __restrict__ olo)
{
    int idx = blockIdx.x * 256 + threadIdx.x;
    int g = idx >> 8;
    int c = idx & 255;
    float m = -1e30f;
    const float* base = z + (size_t)g * MAXN * HH + c;
    for (int n = 0; n < MAXN; n++) m = fmaxf(m, base[(size_t)n * HH]);
    o1[idx] = m;
    __nv_bfloat16 h, l;
    split_bf16(m, h, l);
    ohi[idx] = h; olo[idx] = l;
}

// ---------------- launcher ----------------
extern "C" void kernel_launch(void* const* d_in, const int* in_sizes, int n_in,
                              void* d_out, int out_size)
{
    const float* x   = (const float*)d_in[0];
    const int*   src = (const int*)d_in[1];
    const int*   dst = (const int*)d_in[2];
    const float* gcn_w0 = (const float*)d_in[3];
    const float* bn_g0  = (const float*)d_in[5];
    const float* bn_b0  = (const float*)d_in[6];
    const float *sc_w0, *sc_b0, *gcn_w1, *bn_g1, *bn_b1, *gcn_w2, *bn_g2, *bn_b2;
    if (in_sizes[7] == FD * HH) {  // reference-signature order
        sc_w0  = (const float*)d_in[7];
        sc_b0  = (const float*)d_in[8];
        gcn_w1 = (const float*)d_in[9];
        bn_g1  = (const float*)d_in[11];
        bn_b1  = (const float*)d_in[12];
        gcn_w2 = (const float*)d_in[13];
        bn_g2  = (const float*)d_in[15];
        bn_b2  = (const float*)d_in[16];
    } else {                        // setup_inputs dict order
        gcn_w1 = (const float*)d_in[7];
        bn_g1  = (const float*)d_in[9];
        bn_b1  = (const float*)d_in[10];
        gcn_w2 = (const float*)d_in[11];
        bn_g2  = (const float*)d_in[13];
        bn_b2  = (const float*)d_in[14];
        sc_w0  = (const float*)d_in[15];
        sc_b0  = (const float*)d_in[16];
    }
    const float* edge_w = (const float*)d_in[17];
    const float* fd_w0  = (const float*)d_in[18];
    const float* fd_b0  = (const float*)d_in[19];
    const float* fd_g0  = (const float*)d_in[20];
    const float* fd_be0 = (const float*)d_in[21];
    const float* fd_w1  = (const float*)d_in[22];
    const float* fd_b1  = (const float*)d_in[23];
    const float* fd_g1  = (const float*)d_in[24];
    const float* fd_be1 = (const float*)d_in[25];
    const float* fd_w2  = (const float*)d_in[26];
    const float* fd_b2  = (const float*)d_in[27];
    const float* ph_w0  = (const float*)d_in[28];
    const float* ph_b0  = (const float*)d_in[29];
    const float* ph_w1  = (const float*)d_in[30];
    const float* ph_b1  = (const float*)d_in[31];

    float* out = (float*)d_out;
    float* out_z   = out;
    float* out_adj = out + (size_t)NN * HH;
    float* out_xr  = out_adj + (size_t)BB * MAXN * MAXN;
    float* out_zg  = out_xr + (size_t)NN * FD;
    float* out_mlp = out_zg + (size_t)BB * HH;

    float *pA, *pB, *pC, *pZ;
    cudaGetSymbolAddress((void**)&pA, g_bufA);
    cudaGetSymbolAddress((void**)&pB, g_bufB);
    cudaGetSymbolAddress((void**)&pC, g_bufC);
    cudaGetSymbolAddress((void**)&pZ, g_z);
    __nv_bfloat16 *p0h, *p0l, *p1h, *p1l, *s0h, *s0l, *s1h, *s1l, *wh, *wl;
    cudaGetSymbolAddress((void**)&p0h, g_p0hi);
    cudaGetSymbolAddress((void**)&p0l, g_p0lo);
    cudaGetSymbolAddress((void**)&p1h, g_p1hi);
    cudaGetSymbolAddress((void**)&p1l, g_p1lo);
    cudaGetSymbolAddress((void**)&s0h, g_s0hi);
    cudaGetSymbolAddress((void**)&s0l, g_s0lo);
    cudaGetSymbolAddress((void**)&s1h, g_s1hi);
    cudaGetSymbolAddress((void**)&s1l, g_s1lo);
    cudaGetSymbolAddress((void**)&wh, g_whi);
    cudaGetSymbolAddress((void**)&wl, g_wlo);

    const int SMEM_SZ = 2 * STAGEB;  // 81920
    cudaFuncSetAttribute(mma_gemm<false>,
                         cudaFuncAttributeMaxDynamicSharedMemorySize, SMEM_SZ);
    cudaFuncSetAttribute(mma_gemm<true>,
                         cudaFuncAttributeMaxDynamicSharedMemorySize, SMEM_SZ);

    // ---- graph structure precompute ----
    k_zero_deg<<<NN / 256, 256>>>();
    k_count_deg<<<EE / 256, 256>>>(dst);
    k_dinv<<<NN / 256, 256>>>();
    k_scan_rows<<<BB, 128>>>();
    k_fill_csr<<<EE / 256, 256>>>(src, dst);

    // ---- operand conversion: x and all weights ----
    a_conv<<<NN * FD / 256, 256>>>(x, p0h, p0l, NN * FD);
    // 0 gcn_w0,1 sc_w0,2 gcn_w1,3 gcn_w2,4 edge_w,5 fd_w0,6 fd_w1,7 fd_w2,8 ph_w0,9 ph_w1
    w_conv<<<FD * HH / 256, 256>>>(gcn_w0, wh + 0 * 65536, wl + 0 * 65536, FD, HH);
    w_conv<<<FD * HH / 256, 256>>>(sc_w0,  wh + 1 * 65536, wl + 1 * 65536, FD, HH);
    w_conv<<<HH * HH / 256, 256>>>(gcn_w1, wh + 2 * 65536, wl + 2 * 65536, HH, HH);
    w_conv<<<HH * HH / 256, 256>>>(gcn_w2, wh + 3 * 65536, wl + 3 * 65536, HH, HH);
    w_conv<<<HH * HH / 256, 256>>>(edge_w, wh + 4 * 65536, wl + 4 * 65536, HH, HH);
    w_conv<<<HH * HH / 256, 256>>>(fd_w0,  wh + 5 * 65536, wl + 5 * 65536, HH, HH);
    w_conv<<<HH * HH / 256, 256>>>(fd_w1,  wh + 6 * 65536, wl + 6 * 65536, HH, HH);
    w_conv<<<HH * FD / 256, 256>>>(fd_w2,  wh + 7 * 65536, wl + 7 * 65536, HH, FD);
    w_conv<<<HH * HH / 256, 256>>>(ph_w0,  wh + 8 * 65536, wl + 8 * 65536, HH, HH);
    w_conv<<<HH * HH / 256, 256>>>(ph_w1,  wh + 9 * 65536, wl + 9 * 65536, HH, HH);

    dim3 gBig(NN / 128, HH / 128);   // (256, 2)
    dim3 gXr(NN / 128, FD / 128);    // (256, 1)
    dim3 gAdj(NN / 128, 1);          // (256, 1)
    dim3 gPh(BB / 128, HH / 128);    // (2, 2)

    // ---- block 0: gcn0 (K=128) + shortcut + bn ----
    mma_gemm<false><<<gBig, 256, SMEM_SZ>>>(p0h, p0l, wh + 0 * 65536, wl + 0 * 65536,
                                            nullptr, pA, nullptr, nullptr, FD, HH, 0);
    mma_gemm<false><<<gBig, 256, SMEM_SZ>>>(p0h, p0l, wh + 1 * 65536, wl + 1 * 65536,
                                            sc_b0, pC, nullptr, nullptr, FD, HH, 0);
    aggregate<<<BB, 256>>>(pA, pB);
    k_zero_stats<<<1, 512>>>();
    bn_stats<<<256, 256>>>(pB);
    bn_apply<<<NN * HH / 256, 256>>>(pB, pC, bn_g0, bn_b0, pZ, p0h, p0l, 1);

    // ---- block 1 ----
    mma_gemm<false><<<gBig, 256, SMEM_SZ>>>(p0h, p0l, wh + 2 * 65536, wl + 2 * 65536,
                                            nullptr, pA, nullptr, nullptr, HH, HH, 0);
    aggregate<<<BB, 256>>>(pA, pB);
    k_zero_stats<<<1, 512>>>();
    bn_stats<<<256, 256>>>(pB);
    bn_apply<<<NN * HH / 256, 256>>>(pB, pZ, bn_g1, bn_b1, pZ, p0h, p0l, 1);

    // ---- block 2 ----
    mma_gemm<false><<<gBig, 256, SMEM_SZ>>>(p0h, p0l, wh + 3 * 65536, wl + 3 * 65536,
                                            nullptr, pA, nullptr, nullptr, HH, HH, 0);
    aggregate<<<BB, 256>>>(pA, pB);
    k_zero_stats<<<1, 512>>>();
    bn_stats<<<256, 256>>>(pB);
    bn_apply<<<NN * HH / 256, 256>>>(pB, pZ, bn_g2, bn_b2, pZ, nullptr, nullptr, 1);

    // ---- l2 normalize -> z (output 0) + bf16 emit ----
    l2norm<<<NN / 8, 256>>>(pZ, pZ, out_z, p0h, p0l);

    // ---- edge decoder: zw = z @ edge_w (bf16 emit), adj = sigmoid(zw z^T) ----
    mma_gemm<false><<<gBig, 256, SMEM_SZ>>>(p0h, p0l, wh + 4 * 65536, wl + 4 * 65536,
                                            nullptr, nullptr, p1h, p1l, HH, HH, 0);
    mma_gemm<true><<<gAdj, 256, SMEM_SZ>>>(p1h, p1l, p0h, p0l,
                                           nullptr, out_adj, nullptr, nullptr, HH, MAXN, 0);

    // ---- feature decoder ----
    mma_gemm<false><<<gBig, 256, SMEM_SZ>>>(p0h, p0l, wh + 5 * 65536, wl + 5 * 65536,
                                            fd_b0, pB, nullptr, nullptr, HH, HH, 1);
    k_zero_stats<<<1, 512>>>();
    bn_stats<<<256, 256>>>(pB);
    bn_apply<<<NN * HH / 256, 256>>>(pB, nullptr, fd_g0, fd_be0, pC, p1h, p1l, 0);
    mma_gemm<false><<<gBig, 256, SMEM_SZ>>>(p1h, p1l, wh + 6 * 65536, wl + 6 * 65536,
                                            fd_b1, pB, nullptr, nullptr, HH, HH, 1);
    k_zero_stats<<<1, 512>>>();
    bn_stats<<<256, 256>>>(pB);
    bn_apply<<<NN * HH / 256, 256>>>(pB, nullptr, fd_g1, fd_be1, pC, p0h, p0l, 0);
    mma_gemm<false><<<gXr, 256, SMEM_SZ>>>(p0h, p0l, wh + 7 * 65536, wl + 7 * 65536,
                                           fd_b2, out_xr, nullptr, nullptr, HH, FD, 0);

    // ---- pooling head ----
    maxpool<<<BB * HH / 256, 256>>>(pZ, out_zg, s0h, s0l);
    mma_gemm<false><<<gPh, 256, SMEM_SZ>>>(s0h, s0l, wh + 8 * 65536, wl + 8 * 65536,
                                           ph_b0, nullptr, s1h, s1l, HH, HH, 1);
    mma_gemm<false><<<gPh, 256, SMEM_SZ>>>(s1h, s1l, wh + 9 * 65536, wl + 9 * 65536,
                                           ph_b1, out_mlp, nullptr, nullptr, HH, HH, 0);
}

// round 4
// speedup vs baseline: 1.6018x; 1.2223x over previous
#include <cuda_runtime.h>
#include <cuda_bf16.h>
#include <math.h>
#include <stdint.h>

// Problem constants
#define NN   32768      // nodes
#define HH   256        // hidden
#define FD   128        // input feature dim
#define BB   256        // graphs
#define MAXN 128        // nodes per graph
#define EE   524288     // edges
#define EPG  2048       // edges per graph (EE/BB)

// ======================= PTX helpers (baseline compute_100 only) =======================
__device__ __forceinline__ uint32_t smem_to_u32(const void* smem_ptr) {
    uint32_t addr;
    asm("{ .reg .u64 tmp; cvta.to.shared.u64 tmp, %1; cvt.u32.u64 %0, tmp; }"
        : "=r"(addr) : "l"(smem_ptr));
    return addr;
}
__device__ __forceinline__ void ldsm4(uint32_t* r, uint32_t addr) {
    asm volatile("ldmatrix.sync.aligned.m8n8.x4.shared.b16 {%0,%1,%2,%3}, [%4];"
        : "=r"(r[0]), "=r"(r[1]), "=r"(r[2]), "=r"(r[3]) : "r"(addr));
}
__device__ __forceinline__ void mma16816(float* d, const uint32_t* a, uint32_t b0, uint32_t b1) {
    asm volatile(
        "mma.sync.aligned.m16n8k16.row.col.f32.bf16.bf16.f32 "
        "{%0,%1,%2,%3}, {%4,%5,%6,%7}, {%8,%9}, {%0,%1,%2,%3};"
        : "+f"(d[0]), "+f"(d[1]), "+f"(d[2]), "+f"(d[3])
        : "r"(a[0]), "r"(a[1]), "r"(a[2]), "r"(a[3]), "r"(b0), "r"(b1));
}
__device__ __forceinline__ void cp16(uint32_t s, const void* g) {
    asm volatile("cp.async.cg.shared.global [%0], [%1], 16;" :: "r"(s), "l"(g) : "memory");
}
__device__ __forceinline__ void cp_commit() {
    asm volatile("cp.async.commit_group;" ::: "memory");
}
template<int NG> __device__ __forceinline__ void cp_wait() {
    asm volatile("cp.async.wait_group %0;" :: "n"(NG) : "memory");
}

// ---------------- scratch (device globals) ----------------
__device__ __align__(256) float g_bufA[(size_t)NN * HH];
__device__ __align__(256) float g_bufB[(size_t)NN * HH];
__device__ __align__(256) float g_bufC[(size_t)NN * HH];
__device__ __align__(256) float g_z[(size_t)NN * HH];
__device__ float g_dinv[NN];
__device__ int   g_deg[NN];
__device__ int   g_rowstart[NN];
__device__ int   g_cursor[NN];
__device__ int   g_csr_src[EE];
__device__ float g_csr_norm[EE];
__device__ float g_stats[2 * HH];

// bf16 hi/lo operand buffers
__device__ __align__(256) __nv_bfloat16 g_p0hi[(size_t)NN * HH];
__device__ __align__(256) __nv_bfloat16 g_p0lo[(size_t)NN * HH];
__device__ __align__(256) __nv_bfloat16 g_p1hi[(size_t)NN * HH];
__device__ __align__(256) __nv_bfloat16 g_p1lo[(size_t)NN * HH];
__device__ __align__(256) __nv_bfloat16 g_s0hi[BB * HH];
__device__ __align__(256) __nv_bfloat16 g_s0lo[BB * HH];
__device__ __align__(256) __nv_bfloat16 g_s1hi[BB * HH];
__device__ __align__(256) __nv_bfloat16 g_s1lo[BB * HH];
__device__ __align__(256) __nv_bfloat16 g_whi[10 * 65536];  // 10 transposed weights
__device__ __align__(256) __nv_bfloat16 g_wlo[10 * 65536];

// ---------------- precompute: degrees, dinv, CSR ----------------
__global__ void k_zero_deg() {
    int n = blockIdx.x * 256 + threadIdx.x;
    if (n < NN) g_deg[n] = 0;
}
__global__ void k_count_deg(const int* __restrict__ dst) {
    int e = blockIdx.x * 256 + threadIdx.x;
    if (e >= EE) return;
    int g = e >> 11;
    atomicAdd(&g_deg[g * MAXN + dst[e]], 1);
}
__global__ void k_dinv() {
    int n = blockIdx.x * 256 + threadIdx.x;
    if (n >= NN) return;
    g_dinv[n] = rsqrtf((float)(g_deg[n] + 1));
}
__global__ void k_scan_rows() {
    int g = blockIdx.x;
    int t = threadIdx.x;
    int n = g * MAXN + t;
    __shared__ int s[MAXN];
    int d = g_deg[n];
    s[t] = d;
    __syncthreads();
    for (int off = 1; off < MAXN; off <<= 1) {
        int v = (t >= off) ? s[t - off] : 0;
        __syncthreads();
        s[t] += v;
        __syncthreads();
    }
    int start = g * EPG + s[t] - d;
    g_rowstart[n] = start;
    g_cursor[n] = start;
}
__global__ void k_fill_csr(const int* __restrict__ src, const int* __restrict__ dst) {
    int e = blockIdx.x * 256 + threadIdx.x;
    if (e >= EE) return;
    int g = e >> 11;
    int s = src[e], d = dst[e];
    int slot = atomicAdd(&g_cursor[g * MAXN + d], 1);
    g_csr_src[slot] = s;
    g_csr_norm[slot] = g_dinv[g * MAXN + s] * g_dinv[g * MAXN + d];
}

// ---------------- fp32 -> bf16 hi/lo converts ----------------
__device__ __forceinline__ void split_bf16(float v, __nv_bfloat16& h, __nv_bfloat16& l) {
    h = __float2bfloat16(v);
    l = __float2bfloat16(v - __bfloat162float(h));
}
__global__ void a_conv(const float* __restrict__ A, __nv_bfloat16* __restrict__ hi,
                       __nv_bfloat16* __restrict__ lo, int n) {
    int i = blockIdx.x * 256 + threadIdx.x;
    if (i >= n) return;
    __nv_bfloat16 h, l;
    split_bf16(A[i], h, l);
    hi[i] = h; lo[i] = l;
}
// all 10 weights in one launch: W[K,N] fp32 -> hi/lo[N,K] bf16 at slot w*65536
struct WList { const float* w[10]; int kd[10]; int nd[10]; };
__global__ void w_conv_all(WList wl, __nv_bfloat16* __restrict__ hi,
                           __nv_bfloat16* __restrict__ lo) {
    int widx = blockIdx.y;
    int i = blockIdx.x * 256 + threadIdx.x;
    int Kd = wl.kd[widx], Nd = wl.nd[widx];
    if (i >= Kd * Nd) return;
    int k = i / Nd, n = i - k * Nd;
    __nv_bfloat16 h, l;
    split_bf16(wl.w[widx][i], h, l);
    hi[(size_t)widx * 65536 + (size_t)n * Kd + k] = h;
    lo[(size_t)widx * 65536 + (size_t)n * Kd + k] = l;
}

// ======================= mma.sync split-x3 GEMM =======================
// C[M,Ncols] = A[M,K] @ B[Ncols,K]^T via bf16 hi/lo x3, fp32 accumulate.
// CTA: 128(M) x 128(N) tile, 8 warps (4x2), warp tile 32x64; 2 CTAs/SM.
// K chunks of 32, cp.async double-buffered. SMEM rows padded to 80B.
#define ROWB   80
#define MATB   10240            // 128 rows * 80B
#define STAGEB 40960            // 4 matrices (Ahi,Alo,Bhi,Blo)
template<bool ADJ>
__global__ void __launch_bounds__(256, 2)
mma_gemm(const __nv_bfloat16* __restrict__ Ahi, const __nv_bfloat16* __restrict__ Alo,
         const __nv_bfloat16* __restrict__ Bhi, const __nv_bfloat16* __restrict__ Blo,
         const float* __restrict__ bias, float* __restrict__ Cf,
         __nv_bfloat16* __restrict__ Chi, __nv_bfloat16* __restrict__ Clo,
         int K, int Ncols, int relu)
{
    extern __shared__ char smem[];
    const uint32_t sb = smem_to_u32(smem);
    const int tid = threadIdx.x;
    const int lane = tid & 31;
    const int wid = tid >> 5;
    const int warp_m = wid & 3;        // 4 warps along M
    const int warp_n = wid >> 2;       // 2 warps along N
    const int mrow0 = blockIdx.x * 128;
    const int bn0 = blockIdx.y * 128;
    const int brow0 = ADJ ? mrow0 : bn0;

    const __nv_bfloat16* baseA_hi = Ahi + (size_t)mrow0 * K;
    const __nv_bfloat16* baseA_lo = Alo + (size_t)mrow0 * K;
    const __nv_bfloat16* baseB_hi = Bhi + (size_t)brow0 * K;
    const __nv_bfloat16* baseB_lo = Blo + (size_t)brow0 * K;

    float acc[2][8][4];
#pragma unroll
    for (int mt = 0; mt < 2; mt++)
#pragma unroll
        for (int nt = 0; nt < 8; nt++)
#pragma unroll
            for (int v = 0; v < 4; v++) acc[mt][nt][v] = 0.f;

    auto load_chunk = [&](int c, int stage) {
        const int kc = c << 5;
        const uint32_t sbase = sb + stage * STAGEB;
#pragma unroll
        for (int t = 0; t < 8; t++) {
            int i = t * 256 + tid;
            int mat = i >> 9;               // constant per unrolled t
            int r = (i >> 2) & 127;
            int q = i & 3;
            const __nv_bfloat16* g;
            if      (mat == 0) g = baseA_hi + (size_t)r * K + kc + q * 8;
            else if (mat == 1) g = baseA_lo + (size_t)r * K + kc + q * 8;
            else if (mat == 2) g = baseB_hi + (size_t)r * K + kc + q * 8;
            else               g = baseB_lo + (size_t)r * K + kc + q * 8;
            cp16(sbase + mat * MATB + r * ROWB + q * 16, g);
        }
    };

    auto compute_chunk = [&](int stage) {
        const uint32_t sA = sb + stage * STAGEB;
        const uint32_t sB = sA + 2 * MATB;
#pragma unroll
        for (int ks = 0; ks < 2; ks++) {
            const uint32_t koff = ks * 32 + (lane >> 4) * 16;
            uint32_t ahi[2][4], alo[2][4];
#pragma unroll
            for (int mt = 0; mt < 2; mt++) {
                uint32_t ad = sA + (uint32_t)((warp_m * 32 + mt * 16 + (lane & 15)) * ROWB) + koff;
                ldsm4(ahi[mt], ad);
                ldsm4(alo[mt], ad + MATB);
            }
            // B fragments in two halves (register pressure: enables 2 CTAs/SM)
#pragma unroll
            for (int half = 0; half < 2; half++) {
                uint32_t bhiR[2][4], bloR[2][4];
#pragma unroll
                for (int g2 = 0; g2 < 2; g2++) {
                    uint32_t ad = sB + (uint32_t)((warp_n * 64 + (half * 2 + g2) * 16
                                   + (lane & 15)) * ROWB) + koff;
                    ldsm4(bhiR[g2], ad);
                    ldsm4(bloR[g2], ad + MATB);
                }
#pragma unroll
                for (int mt = 0; mt < 2; mt++)
#pragma unroll
                    for (int nt = 0; nt < 4; nt++) {
                        int g2 = nt >> 1, s = nt & 1;
                        float* ac = acc[mt][half * 4 + nt];
                        mma16816(ac, ahi[mt], bhiR[g2][s], bhiR[g2][s + 2]);
                        mma16816(ac, ahi[mt], bloR[g2][s], bloR[g2][s + 2]);
                        mma16816(ac, alo[mt], bhiR[g2][s], bhiR[g2][s + 2]);
                    }
            }
        }
    };

    const int nch = K >> 5;
    load_chunk(0, 0);
    cp_commit();
    for (int c = 0; c < nch; c++) {
        if (c + 1 < nch) {
            load_chunk(c + 1, (c + 1) & 1);
            cp_commit();
            cp_wait<1>();
        } else {
            cp_wait<0>();
        }
        __syncthreads();
        compute_chunk(c & 1);
        __syncthreads();
    }

    // ---- epilogue (register-resident) ----
    const int r0 = lane >> 2;
    const int cq = (lane & 3) * 2;
#pragma unroll
    for (int mt = 0; mt < 2; mt++) {
#pragma unroll
        for (int nt = 0; nt < 8; nt++) {
            int col = bn0 + warp_n * 64 + nt * 8 + cq;
            float bv0 = 0.f, bv1 = 0.f;
            if (bias) { bv0 = bias[col]; bv1 = bias[col + 1]; }
#pragma unroll
            for (int h = 0; h < 2; h++) {
                int row = mrow0 + warp_m * 32 + mt * 16 + r0 + h * 8;
                float v0 = acc[mt][nt][h * 2 + 0] + bv0;
                float v1 = acc[mt][nt][h * 2 + 1] + bv1;
                if (relu) { v0 = fmaxf(v0, 0.f); v1 = fmaxf(v1, 0.f); }
                if (ADJ) {
                    v0 = 1.f / (1.f + __expf(-v0));
                    v1 = 1.f / (1.f + __expf(-v1));
                    int rl = row - mrow0;
                    int cl = col;
                    if (rl == cl) v0 = 0.f;
                    if (rl == cl + 1) v1 = 0.f;
                    *(float2*)(Cf + (size_t)blockIdx.x * (MAXN * MAXN)
                               + (size_t)rl * MAXN + cl) = make_float2(v0, v1);
                } else {
                    size_t o = (size_t)row * Ncols + col;
                    if (Cf) *(float2*)(Cf + o) = make_float2(v0, v1);
                    if (Chi) {
                        __nv_bfloat16 h0, l0, h1, l1;
                        split_bf16(v0, h0, l0);
                        split_bf16(v1, h1, l1);
                        __nv_bfloat162 ph = {h0, h1}, pl = {l0, l1};
                        *(__nv_bfloat162*)(Chi + o) = ph;
                        *(__nv_bfloat162*)(Clo + o) = pl;
                    }
                }
            }
        }
    }
}

// ---------------- per-graph GCN aggregation + fused BN stats ----------------
// out[n] = dinv[n]^2 * hw[n] + sum_{e: dst=n} norm_e * hw[src_e]
// 128-col chunks (2 passes), float4/lane; per-CTA column stats -> global atomics.
__global__ void __launch_bounds__(256)
aggregate(const float* __restrict__ hw, float* __restrict__ outp, int do_stats) {
    extern __shared__ float sh[];           // 128 x 128 fp32 (64KB)
    __shared__ float sstat[512];
    int g = blockIdx.x;
    int tid = threadIdx.x;
    int lane = tid & 31;
    int w = tid >> 5;
    int nbase = g * MAXN;
    if (do_stats) { sstat[tid] = 0.f; sstat[tid + 256] = 0.f; }
    for (int q = 0; q < 2; q++) {
        __syncthreads();
        int c0 = q * 128;
        for (int i = tid; i < 128 * 32; i += 256) {
            ((float4*)sh)[i] =
                *(const float4*)(hw + (size_t)(nbase + (i >> 5)) * HH + c0 + (i & 31) * 4);
        }
        __syncthreads();
        float ps0 = 0.f, ps1 = 0.f, ps2 = 0.f, ps3 = 0.f;
        float pq0 = 0.f, pq1 = 0.f, pq2 = 0.f, pq3 = 0.f;
        for (int n = w; n < MAXN; n += 8) {
            int gn = nbase + n;
            int rs = g_rowstart[gn];
            int cnt = g_deg[gn];
            float di = g_dinv[gn];
            float sl = di * di;
            float4 self = *(const float4*)&sh[n * 128 + lane * 4];
            float a0 = self.x * sl, a1 = self.y * sl, a2 = self.z * sl, a3 = self.w * sl;
            for (int e = 0; e < cnt; e++) {
                int s = __ldg(&g_csr_src[rs + e]);
                float nm = __ldg(&g_csr_norm[rs + e]);
                float4 p = *(const float4*)&sh[s * 128 + lane * 4];
                a0 = fmaf(p.x, nm, a0);
                a1 = fmaf(p.y, nm, a1);
                a2 = fmaf(p.z, nm, a2);
                a3 = fmaf(p.w, nm, a3);
            }
            *(float4*)(outp + (size_t)gn * HH + c0 + lane * 4) = make_float4(a0, a1, a2, a3);
            if (do_stats) {
                ps0 += a0; ps1 += a1; ps2 += a2; ps3 += a3;
                pq0 = fmaf(a0, a0, pq0); pq1 = fmaf(a1, a1, pq1);
                pq2 = fmaf(a2, a2, pq2); pq3 = fmaf(a3, a3, pq3);
            }
        }
        if (do_stats) {
            int c = c0 + lane * 4;
            atomicAdd(&sstat[c + 0], ps0); atomicAdd(&sstat[c + 1], ps1);
            atomicAdd(&sstat[c + 2], ps2); atomicAdd(&sstat[c + 3], ps3);
            atomicAdd(&sstat[256 + c + 0], pq0); atomicAdd(&sstat[256 + c + 1], pq1);
            atomicAdd(&sstat[256 + c + 2], pq2); atomicAdd(&sstat[256 + c + 3], pq3);
        }
    }
    if (do_stats) {
        __syncthreads();
        atomicAdd(&g_stats[tid], sstat[tid]);
        atomicAdd(&g_stats[tid + 256], sstat[tid + 256]);
    }
}

// ---------------- BatchNorm stats + fused apply (+ bf16 emit) ----------------
__global__ void k_zero_stats() {
    int t = threadIdx.x;
    if (t < 2 * HH) g_stats[t] = 0.f;
}
__global__ void bn_stats(const float* __restrict__ x) {
    int col = threadIdx.x;
    int r0 = blockIdx.x * 128;
    float s = 0.f, q = 0.f;
    for (int r = 0; r < 128; r++) {
        float v = x[(size_t)(r0 + r) * HH + col];
        s += v;
        q = fmaf(v, v, q);
    }
    atomicAdd(&g_stats[col], s);
    atomicAdd(&g_stats[HH + col], q);
}
// mode 0: out = bn(x); mode 1: out = relu(relu(bn(x)) + res); optional bf16 emit
__global__ void bn_apply(const float* __restrict__ xin, const float* __restrict__ res,
                         const float* __restrict__ gam, const float* __restrict__ bet,
                         float* __restrict__ outp,
                         __nv_bfloat16* __restrict__ ohi, __nv_bfloat16* __restrict__ olo,
                         int mode)
{
    size_t idx = (size_t)blockIdx.x * 256 + threadIdx.x;
    int col = (int)(idx & 255);
    const float invN = 1.0f / (float)NN;
    float m = g_stats[col] * invN;
    float var = fmaxf(g_stats[HH + col] * invN - m * m, 0.f);
    float a = gam[col] * rsqrtf(var + 1e-5f);
    float bp = bet[col] - m * a;
    float v = fmaf(xin[idx], a, bp);
    if (mode == 1) {
        v = fmaxf(v, 0.f);
        v = fmaxf(v + res[idx], 0.f);
    }
    outp[idx] = v;
    if (ohi) {
        __nv_bfloat16 h, l;
        split_bf16(v, h, l);
        ohi[idx] = h; olo[idx] = l;
    }
}

// ---------------- row L2 normalize (+ bf16 emit) ----------------
__global__ void l2norm(const float* __restrict__ zin, float* __restrict__ o1,
                       float* __restrict__ o2,
                       __nv_bfloat16* __restrict__ ohi, __nv_bfloat16* __restrict__ olo)
{
    int row = blockIdx.x * 8 + (threadIdx.x >> 5);
    int lane = threadIdx.x & 31;
    const float4* p = (const float4*)(zin + (size_t)row * HH);
    float4 v0 = p[lane], v1 = p[lane + 32];
    float s = v0.x * v0.x + v0.y * v0.y + v0.z * v0.z + v0.w * v0.w
            + v1.x * v1.x + v1.y * v1.y + v1.z * v1.z + v1.w * v1.w;
#pragma unroll
    for (int o = 16; o > 0; o >>= 1) s += __shfl_xor_sync(0xffffffffu, s, o);
    float inv = 1.f / fmaxf(sqrtf(s), 1e-12f);
    float4 w0 = make_float4(v0.x * inv, v0.y * inv, v0.z * inv, v0.w * inv);
    float4 w1 = make_float4(v1.x * inv, v1.y * inv, v1.z * inv, v1.w * inv);
    ((float4*)(o1 + (size_t)row * HH))[lane] = w0;
    ((float4*)(o1 + (size_t)row * HH))[lane + 32] = w1;
    ((float4*)(o2 + (size_t)row * HH))[lane] = w0;
    ((float4*)(o2 + (size_t)row * HH))[lane + 32] = w1;
    const float vv[8] = {w0.x, w0.y, w0.z, w0.w, w1.x, w1.y, w1.z, w1.w};
#pragma unroll
    for (int k = 0; k < 4; k++) {
        __nv_bfloat16 h, l;
        split_bf16(vv[k], h, l);
        ohi[(size_t)row * HH + lane * 4 + k] = h;
        olo[(size_t)row * HH + lane * 4 + k] = l;
        split_bf16(vv[4 + k], h, l);
        ohi[(size_t)row * HH + 128 + lane * 4 + k] = h;
        olo[(size_t)row * HH + 128 + lane * 4 + k] = l;
    }
}

// ---------------- per-graph max pool (+ bf16 emit) ----------------
__global__ void maxpool(const float* __restrict__ z, float* __restrict__ o1,
                        __nv_bfloat16* __restrict__ ohi, __nv_bfloat16* __restrict__ olo)
{
    int idx = blockIdx.x * 256 + threadIdx.x;
    int g = idx >> 8;
    int c = idx & 255;
    float m = -1e30f;
    const float* base = z + (size_t)g * MAXN * HH + c;
    for (int n = 0; n < MAXN; n++) m = fmaxf(m, base[(size_t)n * HH]);
    o1[idx] = m;
    __nv_bfloat16 h, l;
    split_bf16(m, h, l);
    ohi[idx] = h; olo[idx] = l;
}

// ---------------- launcher ----------------
extern "C" void kernel_launch(void* const* d_in, const int* in_sizes, int n_in,
                              void* d_out, int out_size)
{
    const float* x   = (const float*)d_in[0];
    const int*   src = (const int*)d_in[1];
    const int*   dst = (const int*)d_in[2];
    const float* gcn_w0 = (const float*)d_in[3];
    const float* bn_g0  = (const float*)d_in[5];
    const float* bn_b0  = (const float*)d_in[6];
    const float *sc_w0, *sc_b0, *gcn_w1, *bn_g1, *bn_b1, *gcn_w2, *bn_g2, *bn_b2;
    if (in_sizes[7] == FD * HH) {  // reference-signature order
        sc_w0  = (const float*)d_in[7];
        sc_b0  = (const float*)d_in[8];
        gcn_w1 = (const float*)d_in[9];
        bn_g1  = (const float*)d_in[11];
        bn_b1  = (const float*)d_in[12];
        gcn_w2 = (const float*)d_in[13];
        bn_g2  = (const float*)d_in[15];
        bn_b2  = (const float*)d_in[16];
    } else {                        // setup_inputs dict order
        gcn_w1 = (const float*)d_in[7];
        bn_g1  = (const float*)d_in[9];
        bn_b1  = (const float*)d_in[10];
        gcn_w2 = (const float*)d_in[11];
        bn_g2  = (const float*)d_in[13];
        bn_b2  = (const float*)d_in[14];
        sc_w0  = (const float*)d_in[15];
        sc_b0  = (const float*)d_in[16];
    }
    const float* edge_w = (const float*)d_in[17];
    const float* fd_w0  = (const float*)d_in[18];
    const float* fd_b0  = (const float*)d_in[19];
    const float* fd_g0  = (const float*)d_in[20];
    const float* fd_be0 = (const float*)d_in[21];
    const float* fd_w1  = (const float*)d_in[22];
    const float* fd_b1  = (const float*)d_in[23];
    const float* fd_g1  = (const float*)d_in[24];
    const float* fd_be1 = (const float*)d_in[25];
    const float* fd_w2  = (const float*)d_in[26];
    const float* fd_b2  = (const float*)d_in[27];
    const float* ph_w0  = (const float*)d_in[28];
    const float* ph_b0  = (const float*)d_in[29];
    const float* ph_w1  = (const float*)d_in[30];
    const float* ph_b1  = (const float*)d_in[31];

    float* out = (float*)d_out;
    float* out_z   = out;
    float* out_adj = out + (size_t)NN * HH;
    float* out_xr  = out_adj + (size_t)BB * MAXN * MAXN;
    float* out_zg  = out_xr + (size_t)NN * FD;
    float* out_mlp = out_zg + (size_t)BB * HH;

    float *pA, *pB, *pC, *pZ;
    cudaGetSymbolAddress((void**)&pA, g_bufA);
    cudaGetSymbolAddress((void**)&pB, g_bufB);
    cudaGetSymbolAddress((void**)&pC, g_bufC);
    cudaGetSymbolAddress((void**)&pZ, g_z);
    __nv_bfloat16 *p0h, *p0l, *p1h, *p1l, *s0h, *s0l, *s1h, *s1l, *wh, *wl;
    cudaGetSymbolAddress((void**)&p0h, g_p0hi);
    cudaGetSymbolAddress((void**)&p0l, g_p0lo);
    cudaGetSymbolAddress((void**)&p1h, g_p1hi);
    cudaGetSymbolAddress((void**)&p1l, g_p1lo);
    cudaGetSymbolAddress((void**)&s0h, g_s0hi);
    cudaGetSymbolAddress((void**)&s0l, g_s0lo);
    cudaGetSymbolAddress((void**)&s1h, g_s1hi);
    cudaGetSymbolAddress((void**)&s1l, g_s1lo);
    cudaGetSymbolAddress((void**)&wh, g_whi);
    cudaGetSymbolAddress((void**)&wl, g_wlo);

    const int SMEM_SZ = 2 * STAGEB;   // 81920
    const int AGG_SMEM = 128 * 128 * 4;  // 65536
    cudaFuncSetAttribute(mma_gemm<false>,
                         cudaFuncAttributeMaxDynamicSharedMemorySize, SMEM_SZ);
    cudaFuncSetAttribute(mma_gemm<true>,
                         cudaFuncAttributeMaxDynamicSharedMemorySize, SMEM_SZ);
    cudaFuncSetAttribute(aggregate,
                         cudaFuncAttributeMaxDynamicSharedMemorySize, AGG_SMEM);

    // ---- graph structure precompute ----
    k_zero_deg<<<NN / 256, 256>>>();
    k_count_deg<<<EE / 256, 256>>>(dst);
    k_dinv<<<NN / 256, 256>>>();
    k_scan_rows<<<BB, 128>>>();
    k_fill_csr<<<EE / 256, 256>>>(src, dst);

    // ---- operand conversion ----
    a_conv<<<NN * FD / 256, 256>>>(x, p0h, p0l, NN * FD);
    WList wlist;
    wlist.w[0] = gcn_w0; wlist.kd[0] = FD; wlist.nd[0] = HH;
    wlist.w[1] = sc_w0;  wlist.kd[1] = FD; wlist.nd[1] = HH;
    wlist.w[2] = gcn_w1; wlist.kd[2] = HH; wlist.nd[2] = HH;
    wlist.w[3] = gcn_w2; wlist.kd[3] = HH; wlist.nd[3] = HH;
    wlist.w[4] = edge_w; wlist.kd[4] = HH; wlist.nd[4] = HH;
    wlist.w[5] = fd_w0;  wlist.kd[5] = HH; wlist.nd[5] = HH;
    wlist.w[6] = fd_w1;  wlist.kd[6] = HH; wlist.nd[6] = HH;
    wlist.w[7] = fd_w2;  wlist.kd[7] = HH; wlist.nd[7] = FD;
    wlist.w[8] = ph_w0;  wlist.kd[8] = HH; wlist.nd[8] = HH;
    wlist.w[9] = ph_w1;  wlist.kd[9] = HH; wlist.nd[9] = HH;
    w_conv_all<<<dim3(256, 10), 256>>>(wlist, wh, wl);

    dim3 gBig(NN / 128, HH / 128);   // (256, 2)
    dim3 gXr(NN / 128, FD / 128);    // (256, 1)
    dim3 gAdj(NN / 128, 1);          // (256, 1)
    dim3 gPh(BB / 128, HH / 128);    // (2, 2)

    // ---- block 0: gcn0 (K=128) + shortcut + bn ----
    mma_gemm<false><<<gBig, 256, SMEM_SZ>>>(p0h, p0l, wh + 0 * 65536, wl + 0 * 65536,
                                            nullptr, pA, nullptr, nullptr, FD, HH, 0);
    mma_gemm<false><<<gBig, 256, SMEM_SZ>>>(p0h, p0l, wh + 1 * 65536, wl + 1 * 65536,
                                            sc_b0, pC, nullptr, nullptr, FD, HH, 0);
    k_zero_stats<<<1, 512>>>();
    aggregate<<<BB, 256, AGG_SMEM>>>(pA, pB, 1);
    bn_apply<<<NN * HH / 256, 256>>>(pB, pC, bn_g0, bn_b0, pZ, p0h, p0l, 1);

    // ---- block 1 ----
    mma_gemm<false><<<gBig, 256, SMEM_SZ>>>(p0h, p0l, wh + 2 * 65536, wl + 2 * 65536,
                                            nullptr, pA, nullptr, nullptr, HH, HH, 0);
    k_zero_stats<<<1, 512>>>();
    aggregate<<<BB, 256, AGG_SMEM>>>(pA, pB, 1);
    bn_apply<<<NN * HH / 256, 256>>>(pB, pZ, bn_g1, bn_b1, pZ, p0h, p0l, 1);

    // ---- block 2 ----
    mma_gemm<false><<<gBig, 256, SMEM_SZ>>>(p0h, p0l, wh + 3 * 65536, wl + 3 * 65536,
                                            nullptr, pA, nullptr, nullptr, HH, HH, 0);
    k_zero_stats<<<1, 512>>>();
    aggregate<<<BB, 256, AGG_SMEM>>>(pA, pB, 1);
    bn_apply<<<NN * HH / 256, 256>>>(pB, pZ, bn_g2, bn_b2, pZ, nullptr, nullptr, 1);

    // ---- l2 normalize -> z (output 0) + bf16 emit ----
    l2norm<<<NN / 8, 256>>>(pZ, pZ, out_z, p0h, p0l);

    // ---- edge decoder: zw = z @ edge_w (bf16 emit), adj = sigmoid(zw z^T) ----
    mma_gemm<false><<<gBig, 256, SMEM_SZ>>>(p0h, p0l, wh + 4 * 65536, wl + 4 * 65536,
                                            nullptr, nullptr, p1h, p1l, HH, HH, 0);
    mma_gemm<true><<<gAdj, 256, SMEM_SZ>>>(p1h, p1l, p0h, p0l,
                                           nullptr, out_adj, nullptr, nullptr, HH, MAXN, 0);

    // ---- feature decoder ----
    mma_gemm<false><<<gBig, 256, SMEM_SZ>>>(p0h, p0l, wh + 5 * 65536, wl + 5 * 65536,
                                            fd_b0, pB, nullptr, nullptr, HH, HH, 1);
    k_zero_stats<<<1, 512>>>();
    bn_stats<<<256, 256>>>(pB);
    bn_apply<<<NN * HH / 256, 256>>>(pB, nullptr, fd_g0, fd_be0, pC, p1h, p1l, 0);
    mma_gemm<false><<<gBig, 256, SMEM_SZ>>>(p1h, p1l, wh + 6 * 65536, wl + 6 * 65536,
                                            fd_b1, pB, nullptr, nullptr, HH, HH, 1);
    k_zero_stats<<<1, 512>>>();
    bn_stats<<<256, 256>>>(pB);
    bn_apply<<<NN * HH / 256, 256>>>(pB, nullptr, fd_g1, fd_be1, pC, p0h, p0l, 0);
    mma_gemm<false><<<gXr, 256, SMEM_SZ>>>(p0h, p0l, wh + 7 * 65536, wl + 7 * 65536,
                                           fd_b2, out_xr, nullptr, nullptr, HH, FD, 0);

    // ---- pooling head ----
    maxpool<<<BB * HH / 256, 256>>>(pZ, out_zg, s0h, s0l);
    mma_gemm<false><<<gPh, 256, SMEM_SZ>>>(s0h, s0l, wh + 8 * 65536, wl + 8 * 65536,
                                           ph_b0, nullptr, s1h, s1l, HH, HH, 1);
    mma_gemm<false><<<gPh, 256, SMEM_SZ>>>(s1h, s1l, wh + 9 * 65536, wl + 9 * 65536,
                                           ph_b1, out_mlp, nullptr, nullptr, HH, HH, 0);
}